// round 13
// baseline (speedup 1.0000x reference)
#include <cuda_runtime.h>
#include <stddef.h>
#include <stdint.h>

// Problem constants
#define C_CH   32
#define NROW   1024
#define D_DIM  768
#define BHALF  512
#define RSTRIDE (32 * 768)   // float stride between consecutive batch rows of a channel

// ---- scratch (device globals; no allocation allowed) ----
__device__ float  g_sq[C_CH * NROW];
__device__ float  g_colpart[C_CH * 8 * D_DIM];
__device__ float  g_negc[C_CH];
__device__ double g_acc[C_CH * 3];   // per channel: Sxx, Syy, (Sxy+Syx)

__device__ __forceinline__ const float* row_base(const float* __restrict__ src,
                                                 const float* __restrict__ tgt,
                                                 int c, int i) {
    return (i < BHALF)
        ? src + ((size_t)i * 32 + c) * 768
        : tgt + ((size_t)(i - BHALF) * 32 + c) * 768;
}

// exp2 on the FMA pipe: valid for |x| < 2^22, here x in (-1, +eps]
__device__ __forceinline__ float fast_exp2(float x) {
    float r = x + 12582912.0f;
    int   n = __float_as_int(r);
    float f = x - (r - 12582912.0f);
    float p = 1.5403530e-4f;
    p = fmaf(p, f, 1.3333558e-3f);
    p = fmaf(p, f, 9.6181291e-3f);
    p = fmaf(p, f, 5.5504109e-2f);
    p = fmaf(p, f, 2.4022651e-1f);
    p = fmaf(p, f, 6.9314718e-1f);
    p = fmaf(p, f, 1.0f);
    return __int_as_float(__float_as_int(p) + (n << 23));
}

__device__ __forceinline__ uint32_t smem_u32(const void* p) {
    uint32_t a;
    asm("{ .reg .u64 t; cvta.to.shared.u64 t, %1; cvt.u32.u64 %0, t; }" : "=r"(a) : "l"(p));
    return a;
}
__device__ __forceinline__ void cp16(uint32_t dst, const void* src) {
    asm volatile("cp.async.cg.shared.global [%0], [%1], 16;" :: "r"(dst), "l"(src));
}
#define CP_COMMIT() asm volatile("cp.async.commit_group;" ::: "memory")
#define CP_WAIT(n)  asm volatile("cp.async.wait_group %0;" :: "n"(n) : "memory")

// ---- P1: per-row squared norms (one warp per row) ----
__global__ void psq_kernel(const float* __restrict__ src, const float* __restrict__ tgt) {
    int c    = blockIdx.x;
    int warp = threadIdx.x >> 5, lane = threadIdx.x & 31;
    int i    = blockIdx.y * 8 + warp;
    const float4* rp = (const float4*)row_base(src, tgt, c, i);
    float s = 0.f;
#pragma unroll
    for (int j = 0; j < 6; ++j) {
        float4 v = rp[lane + 32 * j];
        s += v.x * v.x + v.y * v.y + v.z * v.z + v.w * v.w;
    }
#pragma unroll
    for (int off = 16; off; off >>= 1) s += __shfl_down_sync(0xffffffffu, s, off);
    if (lane == 0) g_sq[c * NROW + i] = s;
}

// ---- P2: partial column sums (for bandwidth) ----
__global__ void pcol_kernel(const float* __restrict__ src, const float* __restrict__ tgt) {
    int c = blockIdx.x, part = blockIdx.y;
    int t = threadIdx.x;
    float4 s = make_float4(0.f, 0.f, 0.f, 0.f);
    for (int r = 0; r < 128; ++r) {
        const float4* rp = (const float4*)row_base(src, tgt, c, part * 128 + r);
        float4 v = rp[t];
        s.x += v.x; s.y += v.y; s.z += v.z; s.w += v.w;
    }
    ((float4*)g_colpart)[(c * 8 + part) * 192 + t] = s;
}

// ---- P3: bandwidth coefficient per channel + zero accumulators ----
__global__ void pband_kernel() {
    int c = blockIdx.x, tid = threadIdx.x;
    __shared__ double sh[256];
    double acc = 0.0;
    for (int i = tid; i < NROW; i += 256)
        acc += 2.0 * (double)NROW * (double)g_sq[c * NROW + i];
    for (int d = tid; d < D_DIM; d += 256) {
        float cs = 0.f;
#pragma unroll
        for (int p = 0; p < 8; ++p) cs += g_colpart[(c * 8 + p) * D_DIM + d];
        acc -= 2.0 * (double)cs * (double)cs;
    }
    sh[tid] = acc;
    __syncthreads();
    for (int s = 128; s > 0; s >>= 1) {
        if (tid < s) sh[tid] += sh[tid + s];
        __syncthreads();
    }
    if (tid == 0) {
        double sumd2 = sh[0];
        double bw0 = sumd2 / ((double)NROW * NROW - NROW) / 4.0;
        double bw4 = bw0 * 16.0;
        g_negc[c] = (float)(-1.4426950408889634 / bw4);
        g_acc[c * 3 + 0] = 0.0;
        g_acc[c * 3 + 1] = 0.0;
        g_acc[c * 3 + 2] = 0.0;
    }
}

// ============ main kernel: fp16x3 mma.sync m16n8k16 GEMM + RBF epilogue ============
// Tile 128x128, BK=32. Per slab: cp.async stages raw fp32 (single stage), a convert
// phase splits once into fp16 hi/lo half2 tiles in smem, then the MMA loop does only
// LDS.32 fragment loads + MMAs (no per-fragment ALU/cvt). dot = hi*hi + hi*lo + lo*hi.
#define BM   128
#define BK   32
#define LDK  36    // raw fp32 words/row (144B, 16B-aligned)
#define LDKW 20    // fp16 tile row stride in half2 WORDS (40 halves, 80B/row)

// dynamic smem layout in 4-byte words
#define OFF_RAWA 0
#define OFF_RAWB (BM * LDK)                    // 4608
#define OFF_AH   (2 * BM * LDK)                // 9216
#define OFF_AL   (OFF_AH + BM * LDKW)          // +2560
#define OFF_BH   (OFF_AL + BM * LDKW)
#define OFF_BL   (OFF_BH + BM * LDKW)
#define OFF_SQA  (OFF_BL + BM * LDKW)          // 19456
#define OFF_SQB  (OFF_SQA + BM)
#define OFF_RED  (OFF_SQB + BM)
#define SMEM_WORDS (OFF_RED + 256)             // 19968
#define SMEM_BYTES (SMEM_WORDS * 4)            // 79872

__device__ __forceinline__ void mma_f16(float& c0, float& c1, float& c2, float& c3,
                                        uint32_t a0, uint32_t a1, uint32_t a2, uint32_t a3,
                                        uint32_t b0, uint32_t b1) {
    asm volatile("mma.sync.aligned.m16n8k16.row.col.f32.f16.f16.f32 "
                 "{%0,%1,%2,%3}, {%4,%5,%6,%7}, {%8,%9}, {%0,%1,%2,%3};"
                 : "+f"(c0), "+f"(c1), "+f"(c2), "+f"(c3)
                 : "r"(a0), "r"(a1), "r"(a2), "r"(a3), "r"(b0), "r"(b1));
}

// split 2 floats -> fp16 hi half2 + fp16 lo half2 (hi = 10-bit trunc, exactly fp16; lo exact residual)
__device__ __forceinline__ void split2(float x, float y, uint32_t& h2, uint32_t& l2) {
    float h0 = __uint_as_float(__float_as_uint(x) & 0xFFFFE000u);
    float h1 = __uint_as_float(__float_as_uint(y) & 0xFFFFE000u);
    float l0 = x - h0;
    float l1 = y - h1;
    asm("cvt.rn.f16x2.f32 %0, %1, %2;" : "=r"(h2) : "f"(h1), "f"(h0));  // low half = x
    asm("cvt.rn.f16x2.f32 %0, %1, %2;" : "=r"(l2) : "f"(l1), "f"(l0));
}

__global__ __launch_bounds__(256, 2) void mmd_gemm_kernel(const float* __restrict__ src,
                                                          const float* __restrict__ tgt) {
    extern __shared__ uint32_t smw[];
    float*    rawA = (float*)(smw + OFF_RAWA);     // [BM][LDK] fp32
    float*    rawB = (float*)(smw + OFF_RAWB);
    uint32_t* AH   = smw + OFF_AH;                 // [BM][LDKW] half2 words
    uint32_t* AL   = smw + OFF_AL;
    uint32_t* BH   = smw + OFF_BH;
    uint32_t* BL   = smw + OFF_BL;
    float*    sqa_sm = (float*)(smw + OFF_SQA);
    float*    sqb_sm = (float*)(smw + OFF_SQB);
    float*    red    = (float*)(smw + OFF_RED);

    const int c = blockIdx.y;

    // tile index -> upper-triangular (bi, bj), bi <= bj
    int bi = 0, rem = blockIdx.x;
    while (rem >= (8 - bi)) { rem -= (8 - bi); ++bi; }
    const int bj = bi + rem;
    const int i0 = bi * BM, j0 = bj * BM;

    const int tid  = threadIdx.x;
    const int wid  = tid >> 5, lane = tid & 31;
    const int g    = lane >> 2;       // groupID (0..7)
    const int tig  = lane & 3;        // thread-in-group (0..3)
    const int wm0  = (wid >> 2) * 64;
    const int wn0  = (wid & 3) * 32;

    if (tid < 128) sqa_sm[tid] = g_sq[c * NROW + i0 + tid];
    else           sqb_sm[tid - 128] = g_sq[c * NROW + j0 + (tid - 128)];

    // loader mapping: thread -> (row 0..31, kvec 0..7); covers rows {lrow, +32, +64, +96}
    const int lrow = tid >> 3;
    const int lkv  = tid & 7;
    const float* pA = row_base(src, tgt, c, i0) + (size_t)lrow * RSTRIDE + lkv * 4;
    const float* pB = row_base(src, tgt, c, j0) + (size_t)lrow * RSTRIDE + lkv * 4;

    const uint32_t dA = smem_u32(&rawA[lrow * LDK + lkv * 4]);
    const uint32_t dB = smem_u32(&rawB[lrow * LDK + lkv * 4]);
    const uint32_t rowBy = (uint32_t)(32 * LDK * 4);   // 32 raw rows in bytes
    const size_t   rowG  = (size_t)32 * RSTRIDE;

    float cacc[4][4][4];
#pragma unroll
    for (int ma = 0; ma < 4; ++ma)
#pragma unroll
        for (int na = 0; na < 4; ++na)
#pragma unroll
            for (int q = 0; q < 4; ++q) cacc[ma][na][q] = 0.f;

    const int NK = D_DIM / BK;   // 24

    // preload slab 0
#pragma unroll
    for (int p = 0; p < 4; ++p) {
        cp16(dA + p * rowBy, pA + p * rowG);
        cp16(dB + p * rowBy, pB + p * rowG);
    }
    CP_COMMIT();

    for (int ks = 0; ks < NK; ++ks) {
        CP_WAIT(0);
        __syncthreads();   // raw slab ks ready; all warps done with fp16 tiles of ks-1

        // ---- convert phase: split raw fp32 -> fp16 hi/lo tiles (once per element) ----
#pragma unroll
        for (int p = 0; p < 4; ++p) {
            const int row = lrow + 32 * p;
            float4 va = *(const float4*)&rawA[row * LDK + lkv * 4];
            float4 vb = *(const float4*)&rawB[row * LDK + lkv * 4];
            uint32_t h01, l01, h23, l23;
            split2(va.x, va.y, h01, l01);
            split2(va.z, va.w, h23, l23);
            *(uint2*)&AH[row * LDKW + lkv * 2] = make_uint2(h01, h23);
            *(uint2*)&AL[row * LDKW + lkv * 2] = make_uint2(l01, l23);
            split2(vb.x, vb.y, h01, l01);
            split2(vb.z, vb.w, h23, l23);
            *(uint2*)&BH[row * LDKW + lkv * 2] = make_uint2(h01, h23);
            *(uint2*)&BL[row * LDKW + lkv * 2] = make_uint2(l01, l23);
        }
        __syncthreads();   // tiles ready; raw buffers free

        // prefetch next raw slab (overlaps with MMA below)
        if (ks + 1 < NK) {
            const int k0 = (ks + 1) * BK;
#pragma unroll
            for (int p = 0; p < 4; ++p) {
                cp16(dA + p * rowBy, pA + k0 + p * rowG);
                cp16(dB + p * rowBy, pB + k0 + p * rowG);
            }
            CP_COMMIT();
        }

        // ---- MMA loop: pure LDS.32 fragment loads + tensor ops ----
#pragma unroll
        for (int kk2 = 0; kk2 < BK / 2; kk2 += 8) {   // k offset in half2 words
            uint32_t ah[4][4], al[4][4], bh[4][2], bl[4][2];
#pragma unroll
            for (int ma = 0; ma < 4; ++ma) {
                const int base = (wm0 + ma * 16 + g) * LDKW + kk2 + tig;
                ah[ma][0] = AH[base];
                ah[ma][1] = AH[base + 8 * LDKW];
                ah[ma][2] = AH[base + 4];
                ah[ma][3] = AH[base + 8 * LDKW + 4];
                al[ma][0] = AL[base];
                al[ma][1] = AL[base + 8 * LDKW];
                al[ma][2] = AL[base + 4];
                al[ma][3] = AL[base + 8 * LDKW + 4];
            }
#pragma unroll
            for (int na = 0; na < 4; ++na) {
                const int base = (wn0 + na * 8 + g) * LDKW + kk2 + tig;
                bh[na][0] = BH[base];
                bh[na][1] = BH[base + 4];
                bl[na][0] = BL[base];
                bl[na][1] = BL[base + 4];
            }
            // pass 1: hi x hi
#pragma unroll
            for (int ma = 0; ma < 4; ++ma)
#pragma unroll
                for (int na = 0; na < 4; ++na)
                    mma_f16(cacc[ma][na][0], cacc[ma][na][1], cacc[ma][na][2], cacc[ma][na][3],
                            ah[ma][0], ah[ma][1], ah[ma][2], ah[ma][3],
                            bh[na][0], bh[na][1]);
            // pass 2: hi x lo
#pragma unroll
            for (int ma = 0; ma < 4; ++ma)
#pragma unroll
                for (int na = 0; na < 4; ++na)
                    mma_f16(cacc[ma][na][0], cacc[ma][na][1], cacc[ma][na][2], cacc[ma][na][3],
                            ah[ma][0], ah[ma][1], ah[ma][2], ah[ma][3],
                            bl[na][0], bl[na][1]);
            // pass 3: lo x hi
#pragma unroll
            for (int ma = 0; ma < 4; ++ma)
#pragma unroll
                for (int na = 0; na < 4; ++na)
                    mma_f16(cacc[ma][na][0], cacc[ma][na][1], cacc[ma][na][2], cacc[ma][na][3],
                            al[ma][0], al[ma][1], al[ma][2], al[ma][3],
                            bh[na][0], bh[na][1]);
        }
    }

    // ---- epilogue: d2 -> 5-bandwidth RBF sum via one exp2 + 4 squarings ----
    const float negc = g_negc[c];
    float local = 0.f;
#pragma unroll
    for (int ma = 0; ma < 4; ++ma) {
        const float sq_r0 = sqa_sm[wm0 + ma * 16 + g];
        const float sq_r1 = sqa_sm[wm0 + ma * 16 + g + 8];
#pragma unroll
        for (int na = 0; na < 4; ++na) {
            const float sq_c0 = sqb_sm[wn0 + na * 8 + tig * 2];
            const float sq_c1 = sqb_sm[wn0 + na * 8 + tig * 2 + 1];
            float d2v[4];
            d2v[0] = fmaf(-2.0f, cacc[ma][na][0], sq_r0 + sq_c0);
            d2v[1] = fmaf(-2.0f, cacc[ma][na][1], sq_r0 + sq_c1);
            d2v[2] = fmaf(-2.0f, cacc[ma][na][2], sq_r1 + sq_c0);
            d2v[3] = fmaf(-2.0f, cacc[ma][na][3], sq_r1 + sq_c1);
#pragma unroll
            for (int q = 0; q < 4; ++q) {
                float e4 = fast_exp2(d2v[q] * negc);
                float e3 = e4 * e4;
                float e2 = e3 * e3;
                float e1 = e2 * e2;
                float e0 = e1 * e1;
                local += ((e0 + e1) + (e2 + e3)) + e4;
            }
        }
    }

    __syncthreads();
    red[tid] = local;
    __syncthreads();
    for (int s = 128; s > 0; s >>= 1) {
        if (tid < s) red[tid] += red[tid + s];
        __syncthreads();
    }
    if (tid == 0) {
        int region = (bj < 4) ? 0 : ((bi >= 4) ? 1 : 2);   // XX / YY / XY
        double w = (bi == bj) ? 1.0 : 2.0;                 // symmetry weight
        atomicAdd(&g_acc[c * 3 + region], w * (double)red[0]);
    }
}

// ---- finalize: mean over channels of (Sxx + Syy - (Sxy+Syx)) / B^2 ----
__global__ void final_kernel(float* __restrict__ out) {
    int c = threadIdx.x;   // 32 threads
    double mmd = (g_acc[c * 3 + 0] + g_acc[c * 3 + 1] - g_acc[c * 3 + 2])
                 * (1.0 / (512.0 * 512.0));
#pragma unroll
    for (int off = 16; off; off >>= 1)
        mmd += __shfl_down_sync(0xffffffffu, mmd, off);
    if (c == 0) out[0] = (float)(mmd / 32.0);
}

extern "C" void kernel_launch(void* const* d_in, const int* in_sizes, int n_in,
                              void* d_out, int out_size) {
    const float* src = (const float*)d_in[0];
    const float* tgt = (const float*)d_in[1];
    float* out = (float*)d_out;

    cudaFuncSetAttribute(mmd_gemm_kernel, cudaFuncAttributeMaxDynamicSharedMemorySize, SMEM_BYTES);

    psq_kernel<<<dim3(32, 128), 256>>>(src, tgt);
    pcol_kernel<<<dim3(32, 8), 192>>>(src, tgt);
    pband_kernel<<<32, 256>>>();
    mmd_gemm_kernel<<<dim3(36, 32), 256, SMEM_BYTES>>>(src, tgt);
    final_kernel<<<1, 32>>>(out);
}